// round 10
// baseline (speedup 1.0000x reference)
#include <cuda_runtime.h>
#include <cstdint>
#include <cstddef>

// ---------------- problem constants ----------------
#define NTOT   100000
#define NPT    50000
#define NPG    50000
#define EG     500000
#define NG     4
#define NH     4
#define HD     64
#define HID    64
#define DD     256
#define OUTD   64
#define TT     20000

typedef unsigned long long u64;

// ---------------- device scratch (static, no allocs) ----------------
__device__ float g_transformed[(size_t)NTOT * HID];
__device__ u64   g_fcW2[2 * 256 * 64];        // dup fc_W transposed [ty][k][o]
__device__ u64   g_gatW2[4 * 64 * 256];       // dup gat_W [g][k][c]
__device__ u64   g_semW2[2 * 256 * 256];      // dup sem_W [b][k][c]
__device__ u64   g_outW2[2 * 256 * 64];       // dup fcout_W [b][k][o]
__device__ float g_z[(size_t)NG * NPG * DD];
__device__ float g_el[NG * NPG * NH];
__device__ float g_er[NG * NPG * NH];
__device__ int   g_cnt[NG * NPG];
__device__ int   g_cur[NG * NPG];
__device__ int   g_offs[NG * (NPG + 1)];
__device__ int   g_csr[NG * EG];
__device__ int   g_flag[NG * NPG];
__device__ int   g_list[NG * TT];
__device__ int   g_wcnt[NG];
__device__ float g_o[(size_t)NG * NPG * DD];
__device__ float g_wsum[NG];
__device__ float g_beta[NG];

__device__ __forceinline__ float lrelu(float x) { return fmaxf(x, 0.2f * x); }
__device__ __forceinline__ float tanh_fast(float x) {
    float y; asm("tanh.approx.f32 %0, %1;" : "=f"(y) : "f"(x)); return y;
}
__device__ __forceinline__ void fma2(u64& acc, u64 a, u64 b) {
    asm("fma.rn.f32x2 %0, %1, %2, %0;" : "+l"(acc) : "l"(a), "l"(b));
}
__device__ __forceinline__ u64 pack2(float x) {
    u64 d; asm("mov.b64 %0, {%1, %1};" : "=l"(d) : "f"(x)); return d;
}
__device__ __forceinline__ float2 unpack2(u64 v) {
    float2 r; asm("mov.b64 {%0, %1}, %2;" : "=f"(r.x), "=f"(r.y) : "l"(v)); return r;
}
__device__ __forceinline__ u64 add2(u64 a, u64 b) {
    u64 d; asm("add.rn.f32x2 %0, %1, %2;" : "=l"(d) : "l"(a), "l"(b)); return d;
}

// ---------------- dup all GEMM weights into (w,w) u64 form ----------------
__global__ void k_dup(const float* __restrict__ fcW, const float* __restrict__ gatW,
                      const float* __restrict__ semW, const float* __restrict__ foW) {
    int i = blockIdx.x * blockDim.x + threadIdx.x;   // 262144 total
    if (i < 32768) {            // fcW2: transpose [ty][o][k] -> [ty][k][o]
        int ty = i >> 14, rem = i & 16383, k = rem >> 6, o = rem & 63;
        g_fcW2[i] = pack2(fcW[ty * 16384 + o * 256 + k]);
    } else if (i < 98304) {     // gatW2: same linear layout
        int j = i - 32768;
        g_gatW2[j] = pack2(gatW[j]);
    } else if (i < 229376) {    // semW2
        int j = i - 98304;
        g_semW2[j] = pack2(semW[j]);
    } else {                    // outW2
        int j = i - 229376;
        g_outW2[j] = pack2(foW[j]);
    }
}

// ---------------- zero per-call scratch ----------------
__global__ void k_zero() {
    int i = blockIdx.x * blockDim.x + threadIdx.x;
    if (i < NG * NPG) { g_cnt[i] = 0; g_cur[i] = 0; g_flag[i] = 0; }
    if (i < NG) { g_wsum[i] = 0.f; g_wcnt[i] = 0; }
}

// ---------------- 1: type FC (40 rows/block, 160 thr) ----------------
#define FC_PAD 42
__global__ void k_fc(const float* __restrict__ f0, const float* __restrict__ f1,
                     const float* __restrict__ fcb, const int* __restrict__ type_idx) {
    int ty = blockIdx.y;
    int row0 = blockIdx.x * 40;
    __shared__ float sx[256 * FC_PAD];
    int t = threadIdx.x;                      // 160
    const float* f = (ty == 0 ? f0 : f1);
    for (int i = t; i < 40 * 256; i += 160) {
        int r = i >> 8, k = i & 255;
        sx[k * FC_PAD + r] = f[(size_t)(row0 + r) * 256 + k];
    }
    __syncthreads();
    int oq = t & 15, rg = t >> 4;             // rg 0..9, 4 rows (2 pairs)
    const u64* W2 = g_fcW2 + ty * 16384 + oq * 4;
    u64 acc[2][4] = {};
    #pragma unroll 4
    for (int k = 0; k < 256; k++) {
        ulonglong2 wa = *(const ulonglong2*)(W2 + k * 64);
        ulonglong2 wb = *(const ulonglong2*)(W2 + k * 64 + 2);
        u64 x0 = *(const u64*)&sx[k * FC_PAD + rg * 4];
        u64 x1 = *(const u64*)&sx[k * FC_PAD + rg * 4 + 2];
        fma2(acc[0][0], wa.x, x0); fma2(acc[0][1], wa.y, x0);
        fma2(acc[0][2], wb.x, x0); fma2(acc[0][3], wb.y, x0);
        fma2(acc[1][0], wa.x, x1); fma2(acc[1][1], wa.y, x1);
        fma2(acc[1][2], wb.x, x1); fma2(acc[1][3], wb.y, x1);
    }
    float4 bb = *(const float4*)(fcb + ty * 64 + oq * 4);
    #pragma unroll
    for (int p = 0; p < 2; p++) {
        float2 c0 = unpack2(acc[p][0]), c1 = unpack2(acc[p][1]);
        float2 c2 = unpack2(acc[p][2]), c3 = unpack2(acc[p][3]);
        int r0 = row0 + rg * 4 + p * 2;
        int d0 = type_idx[ty * NPT + r0];
        int d1 = type_idx[ty * NPT + r0 + 1];
        *(float4*)(g_transformed + (size_t)d0 * 64 + oq * 4) =
            make_float4(c0.x + bb.x, c1.x + bb.y, c2.x + bb.z, c3.x + bb.w);
        *(float4*)(g_transformed + (size_t)d1 * 64 + oq * 4) =
            make_float4(c0.y + bb.x, c1.y + bb.y, c2.y + bb.z, c3.y + bb.w);
    }
}

// ---------------- 2: gather + z = h @ gat_W, fused el/er (40 rows/block) ----------------
#define GZ_PAD 42
__global__ void k_gatz(const int* __restrict__ node_idx,
                       const float* __restrict__ al, const float* __restrict__ ar) {
    int g = blockIdx.y;
    int row0 = blockIdx.x * 40;
    __shared__ float sx[64 * GZ_PAD];
    int t = threadIdx.x;                      // 256
    for (int i = t; i < 40 * 64; i += 256) {
        int r = i >> 6, k = i & 63;
        int node = node_idx[g * NPG + row0 + r];
        sx[k * GZ_PAD + r] = g_transformed[(size_t)node * 64 + k];
    }
    __syncthreads();
    int jt = t & 63, rg = t >> 6;             // rg 0..3, 10 rows (5 pairs)
    const u64* W2 = g_gatW2 + (size_t)g * 16384 + jt * 4;
    u64 acc[5][4] = {};
    #pragma unroll 2
    for (int k = 0; k < 64; k++) {
        ulonglong2 wa = *(const ulonglong2*)(W2 + k * 256);
        ulonglong2 wb = *(const ulonglong2*)(W2 + k * 256 + 2);
        u64 xp[5];
        #pragma unroll
        for (int p = 0; p < 5; p++) xp[p] = *(const u64*)&sx[k * GZ_PAD + rg * 10 + 2 * p];
        #pragma unroll
        for (int p = 0; p < 5; p++) {
            fma2(acc[p][0], wa.x, xp[p]); fma2(acc[p][1], wa.y, xp[p]);
            fma2(acc[p][2], wb.x, xp[p]); fma2(acc[p][3], wb.y, xp[p]);
        }
    }
    #pragma unroll
    for (int p = 0; p < 5; p++) {
        float2 c0 = unpack2(acc[p][0]), c1 = unpack2(acc[p][1]);
        float2 c2 = unpack2(acc[p][2]), c3 = unpack2(acc[p][3]);
        size_t zb = ((size_t)g * NPG + row0 + rg * 10 + 2 * p) * DD + jt * 4;
        *(float4*)(g_z + zb)      = make_float4(c0.x, c1.x, c2.x, c3.x);
        *(float4*)(g_z + zb + DD) = make_float4(c0.y, c1.y, c2.y, c3.y);
    }
    // fused el/er over 16-lane head group
    float4 alv = *(const float4*)(al + g * DD + jt * 4);
    float4 arv = *(const float4*)(ar + g * DD + jt * 4);
    u64 aL0 = pack2(alv.x), aL1 = pack2(alv.y), aL2 = pack2(alv.z), aL3 = pack2(alv.w);
    u64 aR0 = pack2(arv.x), aR1 = pack2(arv.y), aR2 = pack2(arv.z), aR3 = pack2(arv.w);
    u64 pl[5], pr[5];
    #pragma unroll
    for (int p = 0; p < 5; p++) {
        u64 l = 0, r = 0;
        fma2(l, aL0, acc[p][0]); fma2(l, aL1, acc[p][1]);
        fma2(l, aL2, acc[p][2]); fma2(l, aL3, acc[p][3]);
        fma2(r, aR0, acc[p][0]); fma2(r, aR1, acc[p][1]);
        fma2(r, aR2, acc[p][2]); fma2(r, aR3, acc[p][3]);
        pl[p] = l; pr[p] = r;
    }
    #pragma unroll
    for (int off = 1; off < 16; off <<= 1) {
        #pragma unroll
        for (int p = 0; p < 5; p++) {
            pl[p] = add2(pl[p], __shfl_xor_sync(~0u, pl[p], off));
            pr[p] = add2(pr[p], __shfl_xor_sync(~0u, pr[p], off));
        }
    }
    if ((jt & 15) == 0) {
        int h = jt >> 4;
        #pragma unroll
        for (int p = 0; p < 5; p++) {
            int base = (g * NPG + row0 + rg * 10 + 2 * p) * NH;
            float2 l = unpack2(pl[p]), r = unpack2(pr[p]);
            g_el[base + h]      = l.x;  g_er[base + h]      = r.x;
            g_el[base + NH + h] = l.y;  g_er[base + NH + h] = r.y;
        }
    }
}

// ---------------- 3: CSR build ----------------
__global__ void k_count(const int* __restrict__ edst) {
    int i = blockIdx.x * blockDim.x + threadIdx.x;
    if (i < NG * EG) { int g = i / EG; atomicAdd(&g_cnt[g * NPG + edst[i]], 1); }
}

__global__ void k_scan() {
    int g = blockIdx.x;
    __shared__ int ssum[1024];
    int t = threadIdx.x;
    const int per = (NPG + 1023) / 1024;
    int beg = t * per, end = min(beg + per, NPG);
    int s = 0;
    for (int i = beg; i < end; i++) s += g_cnt[g * NPG + i];
    ssum[t] = s;
    __syncthreads();
    for (int off = 1; off < 1024; off <<= 1) {
        int v = (t >= off) ? ssum[t - off] : 0;
        __syncthreads();
        ssum[t] += v;
        __syncthreads();
    }
    int run = (t == 0) ? 0 : ssum[t - 1];
    for (int i = beg; i < end; i++) { g_offs[g * (NPG + 1) + i] = run; run += g_cnt[g * NPG + i]; }
    if (t == 1023) g_offs[g * (NPG + 1) + NPG] = run;
}

__global__ void k_scatter(const int* __restrict__ esrc, const int* __restrict__ edst) {
    int i = blockIdx.x * blockDim.x + threadIdx.x;
    if (i < NG * EG) {
        int g = i / EG;
        int d = edst[i];
        int pos = g_offs[g * (NPG + 1) + d] + atomicAdd(&g_cur[g * NPG + d], 1);
        g_csr[g * EG + pos] = esrc[i];
    }
}

__global__ void k_flag(const int* __restrict__ tgt) {
    int i = blockIdx.x * blockDim.x + threadIdx.x;
    if (i < NG * TT) {
        int g = i / TT;
        int d = tgt[i];
        if (atomicExch(&g_flag[g * NPG + d], 1) == 0) {
            int p = atomicAdd(&g_wcnt[g], 1);
            g_list[g * TT + p] = d;
        }
    }
}

// ---------------- 4: single-pass edge softmax + aggregation ----------------
__global__ void k_agg() {
    int g = blockIdx.y;
    int widx = blockIdx.x * 8 + (threadIdx.x >> 5);
    if (widx >= g_wcnt[g]) return;
    int lane = threadIdx.x & 31;
    int half = lane >> 4;
    int sub  = lane & 15;
    int h    = sub >> 2;
    int dst  = g_list[g * TT + widx];
    int beg = g_offs[g * (NPG + 1) + dst];
    int end = g_offs[g * (NPG + 1) + dst + 1];
    const int*   csr = g_csr + g * EG;
    const float* elg = g_el + (size_t)g * NPG * NH;
    const float* zg  = g_z + (size_t)g * NPG * DD;
    float erh = g_er[(g * NPG + dst) * NH + h];
    float acc[16] = {};
    float denom = 0.f;
    for (int i = beg + half; i < end; i += 2) {
        int src = csr[i];
        float e  = lrelu(elg[src * NH + h] + erh);
        float ex = __expf(e);
        denom += ex;
        const float4* zp = (const float4*)(zg + (size_t)src * DD + sub * 16);
        float4 a = zp[0], b = zp[1], c = zp[2], d = zp[3];
        acc[0]  += ex * a.x; acc[1]  += ex * a.y; acc[2]  += ex * a.z; acc[3]  += ex * a.w;
        acc[4]  += ex * b.x; acc[5]  += ex * b.y; acc[6]  += ex * b.z; acc[7]  += ex * b.w;
        acc[8]  += ex * c.x; acc[9]  += ex * c.y; acc[10] += ex * c.z; acc[11] += ex * c.w;
        acc[12] += ex * d.x; acc[13] += ex * d.y; acc[14] += ex * d.z; acc[15] += ex * d.w;
    }
    denom += __shfl_xor_sync(~0u, denom, 16);
    #pragma unroll
    for (int j = 0; j < 16; j++) acc[j] += __shfl_xor_sync(~0u, acc[j], 16);
    if (half == 0) {
        float inv = 1.f / (denom + 1e-9f);
        float* op = g_o + ((size_t)g * NPG + dst) * DD + sub * 16;
        float4 v[4];
        #pragma unroll
        for (int j = 0; j < 16; j++) {
            float x = acc[j] * inv;
            ((float*)v)[j] = (x > 0.f) ? x : (__expf(x) - 1.f);
        }
        #pragma unroll
        for (int j = 0; j < 4; j++) ((float4*)op)[j] = v[j];
    }
}

// ---------------- 5: semantic score (64 rows/block, 256 thr, dyn smem) ----------------
#define SEM_PAD 66
__global__ void k_sem(const float* __restrict__ semb,
                      const float* __restrict__ semq, const int* __restrict__ tgt) {
    extern __shared__ float sx[];             // [256][SEM_PAD]
    __shared__ float sred[256];
    int g = blockIdx.y, b = g >> 1;
    int row0 = blockIdx.x * 64;
    int t = threadIdx.x;
    for (int i = t; i < 64 * 256; i += 256) {
        int r = i >> 8, k = i & 255;
        int rr = row0 + r; rr = (rr < TT) ? rr : (TT - 1);
        int node = tgt[g * TT + rr];
        sx[k * SEM_PAD + r] = g_o[((size_t)g * NPG + node) * DD + k];
    }
    __syncthreads();
    int jt = t & 63, rg = t >> 6;             // rg 0..3, 16 rows (8 pairs)
    const u64* W2 = g_semW2 + (size_t)b * 65536 + jt * 4;
    u64 acc[8][4] = {};
    for (int k = 0; k < 256; k++) {
        ulonglong2 wa = *(const ulonglong2*)(W2 + (size_t)k * 256);
        ulonglong2 wb = *(const ulonglong2*)(W2 + (size_t)k * 256 + 2);
        u64 xp[8];
        #pragma unroll
        for (int p = 0; p < 8; p++) xp[p] = *(const u64*)&sx[k * SEM_PAD + rg * 16 + 2 * p];
        #pragma unroll
        for (int p = 0; p < 8; p++) {
            fma2(acc[p][0], wa.x, xp[p]); fma2(acc[p][1], wa.y, xp[p]);
            fma2(acc[p][2], wb.x, xp[p]); fma2(acc[p][3], wb.y, xp[p]);
        }
    }
    float4 bb = *(const float4*)(semb + b * DD + jt * 4);
    float4 qq = *(const float4*)(semq + b * DD + jt * 4);
    float part = 0.f;
    #pragma unroll
    for (int p = 0; p < 8; p++) {
        float2 c0 = unpack2(acc[p][0]), c1 = unpack2(acc[p][1]);
        float2 c2 = unpack2(acc[p][2]), c3 = unpack2(acc[p][3]);
        part += (tanh_fast(c0.x + bb.x) + tanh_fast(c0.y + bb.x)) * qq.x;
        part += (tanh_fast(c1.x + bb.y) + tanh_fast(c1.y + bb.y)) * qq.y;
        part += (tanh_fast(c2.x + bb.z) + tanh_fast(c2.y + bb.z)) * qq.z;
        part += (tanh_fast(c3.x + bb.w) + tanh_fast(c3.y + bb.w)) * qq.w;
    }
    // guard: last block covers rows beyond TT; each thread's 16 rows are all
    // valid or all invalid (TT - row0 is a multiple of 16 in the tail block)
    if (row0 + rg * 16 + 16 > TT) part = 0.f;
    sred[t] = part;
    __syncthreads();
    for (int s2 = 128; s2; s2 >>= 1) {
        if (t < s2) sred[t] += sred[t + s2];
        __syncthreads();
    }
    if (t == 0) atomicAdd(&g_wsum[g], sred[0]);
}

__global__ void k_beta() {
    if (threadIdx.x == 0 && blockIdx.x == 0) {
        for (int b = 0; b < 2; b++) {
            float w0 = g_wsum[b * 2 + 0] / (float)TT;
            float w1 = g_wsum[b * 2 + 1] / (float)TT;
            float mx = fmaxf(w0, w1);
            float e0 = __expf(w0 - mx), e1 = __expf(w1 - mx);
            float s = e0 + e1;
            g_beta[b * 2 + 0] = e0 / s;
            g_beta[b * 2 + 1] = e1 / s;
        }
    }
}

// ---------------- 6: beta-mix + fcout (32 rows/block, 256 thr) ----------------
#define OUT_PAD 34
__global__ void k_out(const float* __restrict__ fob,
                      const int* __restrict__ tgt, float* __restrict__ out) {
    int b = blockIdx.y;
    int row0 = blockIdx.x * 32;
    __shared__ float sx[256 * OUT_PAD];
    int t = threadIdx.x;
    float b0 = g_beta[b * 2], b1 = g_beta[b * 2 + 1];
    for (int i = t; i < 32 * 256; i += 256) {
        int r = i >> 8, k = i & 255;
        int row = row0 + r;
        int n0 = tgt[(b * 2 + 0) * TT + row];
        int n1 = tgt[(b * 2 + 1) * TT + row];
        sx[k * OUT_PAD + r] = b0 * g_o[((size_t)(b * 2 + 0) * NPG + n0) * DD + k]
                            + b1 * g_o[((size_t)(b * 2 + 1) * NPG + n1) * DD + k];
    }
    __syncthreads();
    int oq = t & 15, rg = t >> 4;             // rg 0..15, 2 rows (1 pair)
    const u64* W2 = g_outW2 + (size_t)b * 16384 + oq * 4;
    u64 acc0 = 0, acc1 = 0, acc2 = 0, acc3 = 0;
    #pragma unroll 4
    for (int k = 0; k < 256; k++) {
        ulonglong2 wa = *(const ulonglong2*)(W2 + k * 64);
        ulonglong2 wb = *(const ulonglong2*)(W2 + k * 64 + 2);
        u64 xp = *(const u64*)&sx[k * OUT_PAD + rg * 2];
        fma2(acc0, wa.x, xp); fma2(acc1, wa.y, xp);
        fma2(acc2, wb.x, xp); fma2(acc3, wb.y, xp);
    }
    float4 bb = *(const float4*)(fob + b * 64 + oq * 4);
    float2 a0 = unpack2(acc0), a1 = unpack2(acc1), a2 = unpack2(acc2), a3 = unpack2(acc3);
    int r0 = row0 + rg * 2;
    *(float4*)(out + ((size_t)b * TT + r0) * OUTD + oq * 4) =
        make_float4(a0.x + bb.x, a1.x + bb.y, a2.x + bb.z, a3.x + bb.w);
    *(float4*)(out + ((size_t)b * TT + r0 + 1) * OUTD + oq * 4) =
        make_float4(a0.y + bb.x, a1.y + bb.y, a2.y + bb.z, a3.y + bb.w);
}

// ---------------- launch ----------------
extern "C" void kernel_launch(void* const* d_in, const int* in_sizes, int n_in,
                              void* d_out, int out_size) {
    const float* features0 = (const float*)d_in[0];
    const float* features1 = (const float*)d_in[1];
    const float* fc_W      = (const float*)d_in[2];
    const float* fc_b      = (const float*)d_in[3];
    const float* gat_W     = (const float*)d_in[4];
    const float* attn_l    = (const float*)d_in[5];
    const float* attn_r    = (const float*)d_in[6];
    const float* sem_W     = (const float*)d_in[7];
    const float* sem_b     = (const float*)d_in[8];
    const float* sem_q     = (const float*)d_in[9];
    const float* fcout_W   = (const float*)d_in[10];
    const float* fcout_b   = (const float*)d_in[11];
    const int*   type_idx  = (const int*)d_in[12];
    const int*   node_idx  = (const int*)d_in[13];
    const int*   edge_src  = (const int*)d_in[14];
    const int*   edge_dst  = (const int*)d_in[15];
    const int*   tgt_idx   = (const int*)d_in[16];
    float* out = (float*)d_out;

    // unconditional (no static state): host-side attribute set is
    // graph-capture-safe and deterministic
    cudaFuncSetAttribute(k_sem, cudaFuncAttributeMaxDynamicSharedMemorySize,
                         256 * SEM_PAD * 4);

    k_dup<<<1024, 256>>>(fc_W, gat_W, sem_W, fcout_W);          // 1
    k_zero<<<(NG * NPG + 255) / 256, 256>>>();                  // 2
    {
        dim3 grid(NPT / 40, 2);
        k_fc<<<grid, 160>>>(features0, features1, fc_b, type_idx);  // 3
    }
    {
        dim3 grid(NPG / 40, NG);
        k_gatz<<<grid, 256>>>(node_idx, attn_l, attn_r);        // 4 <- ncu capture slot
    }
    k_count<<<(NG * EG + 255) / 256, 256>>>(edge_dst);
    k_scan<<<NG, 1024>>>();
    k_scatter<<<(NG * EG + 255) / 256, 256>>>(edge_src, edge_dst);
    k_flag<<<(NG * TT + 255) / 256, 256>>>(tgt_idx);
    {
        dim3 grid((TT + 7) / 8, NG);
        k_agg<<<grid, 256>>>();
    }
    {
        dim3 grid((TT + 63) / 64, NG);
        k_sem<<<grid, 256, 256 * SEM_PAD * 4>>>(sem_b, sem_q, tgt_idx);
    }
    k_beta<<<1, 32>>>();
    {
        dim3 grid(TT / 32, 2);
        k_out<<<grid, 256>>>(fcout_b, tgt_idx, out);
    }
}